// round 3
// baseline (speedup 1.0000x reference)
#include <cuda_runtime.h>

// StateOuterProductCumsum: S[t,b,d,n] = sum_{s<=t} v[s,b,d]*k[s,b,n]*decay[s,b,n]
// decay[t,b,n] = exp(cumsum_t log(max(alpha,1e-8))) / (exp(total) + 1e-8)
// T=1024, B=8, D=64, N=64. Output 134 MB fp32.
//
// R2 finding: hot kernel is LSU store-dispatch bound (8.4M STG.128). Fix:
// 256-bit stores/loads (sm_100a+ v8.f32) halve LSU op count -> ~14-17us floor.

#define T_DIM 1024
#define B_DIM 8
#define D_DIM 64
#define N_DIM 64
#define EPS_F 1e-8f

#define NCHUNK 32
#define CLEN   (T_DIM / NCHUNK)          // 32
#define NCOL   (B_DIM * D_DIM * N_DIM)   // 32768
#define NCOL4  (NCOL / 4)                // 8192
#define NCOL8  (NCOL / 8)                // 4096

__device__ __align__(256) float  g_w  [T_DIM * B_DIM * N_DIM];   // 2 MB
__device__ float4 g_p  [NCHUNK * NCOL4];                          // 4 MB
__device__ float4 g_off[NCHUNK * NCOL4];                          // 4 MB

// ---- 256-bit global memory ops (sm_100a+) ----------------------------------
__device__ __forceinline__ void ldg256(float r[8], const float* p) {
    asm volatile("ld.global.nc.v8.f32 {%0,%1,%2,%3,%4,%5,%6,%7}, [%8];"
                 : "=f"(r[0]), "=f"(r[1]), "=f"(r[2]), "=f"(r[3]),
                   "=f"(r[4]), "=f"(r[5]), "=f"(r[6]), "=f"(r[7])
                 : "l"(p));
}
__device__ __forceinline__ void stg256_cs(float* p, const float r[8]) {
    asm volatile("st.global.cs.v8.f32 [%0], {%1,%2,%3,%4,%5,%6,%7,%8};"
                 :: "l"(p),
                    "f"(r[0]), "f"(r[1]), "f"(r[2]), "f"(r[3]),
                    "f"(r[4]), "f"(r[5]), "f"(r[6]), "f"(r[7])
                 : "memory");
}

// ---------------------------------------------------------------------------
// 1) decay: one block per (b,n); 1024 threads; warp-shfl scan; fast-math MUFU.
__global__ void decay_kernel(const float* __restrict__ k_in,
                             const float* __restrict__ alpha) {
    const int s = blockIdx.x;                 // b*N + n
    const int t = threadIdx.x;                // 0..1023
    const int warp = t >> 5, lane = t & 31;
    const int stride = B_DIM * N_DIM;         // 512

    __shared__ float sh_warp[32];

    float la = __logf(fmaxf(alpha[(size_t)t * stride + s], EPS_F));

    float x = la;
    #pragma unroll
    for (int off = 1; off < 32; off <<= 1) {
        float y = __shfl_up_sync(0xFFFFFFFFu, x, off);
        if (lane >= off) x += y;
    }
    if (lane == 31) sh_warp[warp] = x;
    __syncthreads();

    if (warp == 0) {
        float ws = sh_warp[lane];
        #pragma unroll
        for (int off = 1; off < 32; off <<= 1) {
            float y = __shfl_up_sync(0xFFFFFFFFu, ws, off);
            if (lane >= off) ws += y;
        }
        sh_warp[lane] = ws;
    }
    __syncthreads();

    float cl    = x + ((warp > 0) ? sh_warp[warp - 1] : 0.0f);
    float total = sh_warp[31];
    float inv_den = 1.0f / (__expf(total) + EPS_F);

    // exp underflows to 0 for cl < ~-103, matching the reference fp32 pipeline.
    g_w[(size_t)t * stride + s] =
        k_in[(size_t)t * stride + s] * __expf(cl) * inv_den;
}

// ---------------------------------------------------------------------------
// idx decode (partial & cumsum): n8 (0..7), d (0..63), b (0..7), c (0..31)
// Consecutive lanes -> consecutive n8 -> warp stores 1KB contiguous per (t,d).

// 2) per-chunk partial sums (v8 loads of w)
__global__ void __launch_bounds__(256) partial_kernel(const float* __restrict__ v) {
    const int idx = blockIdx.x * blockDim.x + threadIdx.x;
    const int n8 = idx & 7;
    const int d  = (idx >> 3) & 63;
    const int b  = (idx >> 9) & 7;
    const int c  = idx >> 12;

    const float* vp = v + b * D_DIM + d;
    const float* wp = g_w + b * N_DIM + n8 * 8;
    const int t0 = c * CLEN;

    float acc[8] = {0.f, 0.f, 0.f, 0.f, 0.f, 0.f, 0.f, 0.f};
    #pragma unroll 8
    for (int i = 0; i < CLEN; ++i) {
        const int t = t0 + i;
        float a = __ldg(vp + (size_t)t * (B_DIM * D_DIM));
        float w[8];
        ldg256(w, wp + (size_t)t * (B_DIM * N_DIM));
        #pragma unroll
        for (int j = 0; j < 8; ++j) acc[j] = fmaf(a, w[j], acc[j]);
    }
    const int col8 = (b << 9) + (d << 3) + n8;
    float4* dst = &g_p[c * NCOL4 + col8 * 2];
    dst[0] = make_float4(acc[0], acc[1], acc[2], acc[3]);
    dst[1] = make_float4(acc[4], acc[5], acc[6], acc[7]);
}

// 3) exclusive scan of P over chunks (one thread per col4)
__global__ void scan_kernel() {
    const int col4 = blockIdx.x * blockDim.x + threadIdx.x;
    if (col4 >= NCOL4) return;
    float4 run = make_float4(0.f, 0.f, 0.f, 0.f);
    #pragma unroll
    for (int c = 0; c < NCHUNK; ++c) {
        float4 p = g_p[c * NCOL4 + col4];
        g_off[c * NCOL4 + col4] = run;
        run.x += p.x; run.y += p.y; run.z += p.z; run.w += p.w;
    }
}

// 4) hot kernel: streamed cumsum, 256-bit loads + stores
__global__ void __launch_bounds__(256) cumsum_kernel(const float* __restrict__ v,
                                                     float* __restrict__ out) {
    const int idx = blockIdx.x * blockDim.x + threadIdx.x;
    const int n8 = idx & 7;
    const int d  = (idx >> 3) & 63;
    const int b  = (idx >> 9) & 7;
    const int c  = idx >> 12;

    const int col8 = (b << 9) + (d << 3) + n8;
    const float* vp = v + b * D_DIM + d;
    const float* wp = g_w + b * N_DIM + n8 * 8;
    float*       op = out + col8 * 8;
    const int t0 = c * CLEN;

    float acc[8];
    {
        const float4* offp = &g_off[c * NCOL4 + col8 * 2];
        float4 o0 = offp[0], o1 = offp[1];
        acc[0] = o0.x; acc[1] = o0.y; acc[2] = o0.z; acc[3] = o0.w;
        acc[4] = o1.x; acc[5] = o1.y; acc[6] = o1.z; acc[7] = o1.w;
    }

    #pragma unroll 8
    for (int i = 0; i < CLEN; ++i) {
        const int t = t0 + i;
        float a = __ldg(vp + (size_t)t * (B_DIM * D_DIM));
        float w[8];
        ldg256(w, wp + (size_t)t * (B_DIM * N_DIM));
        #pragma unroll
        for (int j = 0; j < 8; ++j) acc[j] = fmaf(a, w[j], acc[j]);
        stg256_cs(op + (size_t)t * NCOL, acc);
    }
}

// ---------------------------------------------------------------------------
extern "C" void kernel_launch(void* const* d_in, const int* in_sizes, int n_in,
                              void* d_out, int out_size) {
    const float* v     = (const float*)d_in[0];
    const float* k_in  = (const float*)d_in[1];
    const float* alpha = (const float*)d_in[2];
    float* out = (float*)d_out;

    decay_kernel<<<B_DIM * N_DIM, T_DIM>>>(k_in, alpha);

    const int threads = 256;
    const int nthr = NCHUNK * NCOL8;                    // 131072
    partial_kernel<<<nthr / threads, threads>>>(v);     // 512 CTAs
    scan_kernel<<<(NCOL4 + threads - 1) / threads, threads>>>();
    cumsum_kernel<<<nthr / threads, threads>>>(v, out); // 512 CTAs
}